// round 3
// baseline (speedup 1.0000x reference)
#include <cuda_runtime.h>

#define N_LAYERS 32
#define N_SUB    8
#define TPB      256
#define PAIRS    8          // f32x2 chains per thread = 16 elements/thread

typedef unsigned long long u64;

__device__ __forceinline__ u64 pack2(float a, float b) {
    u64 r;
    asm("mov.b64 %0, {%1, %2};" : "=l"(r) : "f"(a), "f"(b));
    return r;
}
__device__ __forceinline__ void unpack2(u64 v, float& a, float& b) {
    asm("mov.b64 {%0, %1}, %2;" : "=f"(a), "=f"(b) : "l"(v));
}
__device__ __forceinline__ u64 fma2(u64 a, u64 b, u64 c) {
    u64 d;
    asm("fma.rn.f32x2 %0, %1, %2, %3;" : "=l"(d) : "l"(a), "l"(b), "l"(c));
    return d;
}

// tanh of both f32 lanes via one MUFU f16x2 op.
__device__ __forceinline__ u64 tanh2(u64 x) {
    float lo, hi;
    asm("mov.b64 {%0, %1}, %2;" : "=f"(lo), "=f"(hi) : "l"(x));
    unsigned th;
    asm("cvt.rn.f16x2.f32 %0, %1, %2;" : "=r"(th) : "f"(hi), "f"(lo));
    asm("tanh.approx.f16x2 %0, %0;" : "+r"(th));
    unsigned short hlo, hhi;
    asm("mov.b32 {%0, %1}, %2;" : "=h"(hlo), "=h"(hhi) : "r"(th));
    float tlo, thi;
    asm("cvt.f32.f16 %0, %1;" : "=f"(tlo) : "h"(hlo));
    asm("cvt.f32.f16 %0, %1;" : "=f"(thi) : "h"(hhi));
    u64 r;
    asm("mov.b64 %0, {%1, %2};" : "=l"(r) : "f"(tlo), "f"(thi));
    return r;
}

#define SIGNMASK2 0x8000000080000000ULL

__global__ __launch_bounds__(TPB, 4)
void sympnet_kernel(const float4* __restrict__ x,
                    const float*  __restrict__ act_w,
                    const float*  __restrict__ bias_b,
                    const float*  __restrict__ lin_w,
                    float4*       __restrict__ out,
                    int n4)
{
    // Per-layer constants, duplicated into both f32x2 lanes:
    // fwd[i] = {aw, m00, m01, c0, m10, m11, c1}
    // inv[i] = {-aw, u00, u01, d0, u10, u11, d1}
    __shared__ u64 s_f[N_LAYERS][7];
    __shared__ u64 s_r[N_LAYERS][7];

    const int t = threadIdx.x;

    if (t < N_LAYERS) {
        const int i = t;
        float m00 = 1.f, m01 = 0.f, m10 = 0.f, m11 = 1.f;
        float c0 = bias_b[2 * i + 0];
        float c1 = bias_b[2 * i + 1];
        #pragma unroll
        for (int j = 0; j < N_SUB; ++j) {
            float w = lin_w[i * N_SUB + j];
            if ((j & 1) == 0) {          // q += w*p
                m00 = fmaf(w, m10, m00);
                m01 = fmaf(w, m11, m01);
                c0  = fmaf(w, c1,  c0);
            } else {                      // p += w*q
                m10 = fmaf(w, m00, m10);
                m11 = fmaf(w, m01, m11);
                c1  = fmaf(w, c0,  c1);
            }
        }
        float aw = act_w[i];
        s_f[i][0] = pack2(aw,  aw);
        s_f[i][1] = pack2(m00, m00);
        s_f[i][2] = pack2(m01, m01);
        s_f[i][3] = pack2(c0,  c0);
        s_f[i][4] = pack2(m10, m10);
        s_f[i][5] = pack2(m11, m11);
        s_f[i][6] = pack2(c1,  c1);
    } else if (t < 2 * N_LAYERS) {
        const int i = t - N_LAYERS;
        float u00 = 1.f, u01 = 0.f, u10 = 0.f, u11 = 1.f;
        float d0 = 0.f, d1 = 0.f;
        #pragma unroll
        for (int j = N_SUB - 1; j >= 0; --j) {
            float w = lin_w[i * N_SUB + j];
            if ((j & 1) == 0) {          // q -= w*p
                u00 = fmaf(-w, u10, u00);
                u01 = fmaf(-w, u11, u01);
                d0  = fmaf(-w, d1,  d0);
            } else {                      // p -= w*q
                u10 = fmaf(-w, u00, u10);
                u11 = fmaf(-w, u01, u11);
                d1  = fmaf(-w, d0,  d1);
            }
        }
        d0 -= bias_b[2 * i + 0];
        d1 -= bias_b[2 * i + 1];
        float naw = -act_w[i];
        s_r[i][0] = pack2(naw, naw);
        s_r[i][1] = pack2(u00, u00);
        s_r[i][2] = pack2(u01, u01);
        s_r[i][3] = pack2(d0,  d0);
        s_r[i][4] = pack2(u10, u10);
        s_r[i][5] = pack2(u11, u11);
        s_r[i][6] = pack2(d1,  d1);
    }
    __syncthreads();

    const int base = blockIdx.x * (TPB * PAIRS) + t;

    u64 q2[PAIRS], p2[PAIRS];
    #pragma unroll
    for (int e = 0; e < PAIRS; ++e) {
        int idx = base + e * TPB;
        if (idx < n4) {
            float4 v = x[idx];            // {q0, p0, q1, p1}
            q2[e] = pack2(v.x, v.z);
            p2[e] = pack2(v.y, v.w);
        } else {
            q2[e] = 0ULL; p2[e] = 0ULL;
        }
    }

    // ---------------- forward chain ----------------
    for (int i = 0; i < N_LAYERS; i += 2) {
        {   // even layer: q += aw*tanh(p), then affine
            u64 aw  = s_f[i][0];
            u64 m00 = s_f[i][1], m01 = s_f[i][2], c0 = s_f[i][3];
            u64 m10 = s_f[i][4], m11 = s_f[i][5], c1 = s_f[i][6];
            #pragma unroll
            for (int e = 0; e < PAIRS; ++e) {
                u64 tq = fma2(aw, tanh2(p2[e]), q2[e]);
                u64 nq = fma2(m00, tq, fma2(m01, p2[e], c0));
                u64 np = fma2(m10, tq, fma2(m11, p2[e], c1));
                q2[e] = nq; p2[e] = np;
            }
        }
        {   // odd layer: p += aw*tanh(q), then affine
            u64 aw  = s_f[i + 1][0];
            u64 m00 = s_f[i + 1][1], m01 = s_f[i + 1][2], c0 = s_f[i + 1][3];
            u64 m10 = s_f[i + 1][4], m11 = s_f[i + 1][5], c1 = s_f[i + 1][6];
            #pragma unroll
            for (int e = 0; e < PAIRS; ++e) {
                u64 tp = fma2(aw, tanh2(q2[e]), p2[e]);
                u64 nq = fma2(m00, q2[e], fma2(m01, tp, c0));
                u64 np = fma2(m10, q2[e], fma2(m11, tp, c1));
                q2[e] = nq; p2[e] = np;
            }
        }
    }

    // time reversal: p = -p
    #pragma unroll
    for (int e = 0; e < PAIRS; ++e) p2[e] ^= SIGNMASK2;

    // ---------------- inverse chain ----------------
    for (int i = N_LAYERS - 2; i >= 0; i -= 2) {
        {   // odd layer i+1: inverse affine, then p -= aw*tanh(q)
            u64 naw = s_r[i + 1][0];
            u64 u00 = s_r[i + 1][1], u01 = s_r[i + 1][2], d0 = s_r[i + 1][3];
            u64 u10 = s_r[i + 1][4], u11 = s_r[i + 1][5], d1 = s_r[i + 1][6];
            #pragma unroll
            for (int e = 0; e < PAIRS; ++e) {
                u64 nq = fma2(u00, q2[e], fma2(u01, p2[e], d0));
                u64 np = fma2(u10, q2[e], fma2(u11, p2[e], d1));
                q2[e] = nq;
                p2[e] = fma2(naw, tanh2(nq), np);
            }
        }
        {   // even layer i: inverse affine, then q -= aw*tanh(p)
            u64 naw = s_r[i][0];
            u64 u00 = s_r[i][1], u01 = s_r[i][2], d0 = s_r[i][3];
            u64 u10 = s_r[i][4], u11 = s_r[i][5], d1 = s_r[i][6];
            #pragma unroll
            for (int e = 0; e < PAIRS; ++e) {
                u64 nq = fma2(u00, q2[e], fma2(u01, p2[e], d0));
                u64 np = fma2(u10, q2[e], fma2(u11, p2[e], d1));
                p2[e] = np;
                q2[e] = fma2(naw, tanh2(np), nq);
            }
        }
    }

    // output: (q, -p)
    #pragma unroll
    for (int e = 0; e < PAIRS; ++e) {
        int idx = base + e * TPB;
        if (idx < n4) {
            u64 pneg = p2[e] ^ SIGNMASK2;
            float q0, q1, pn0, pn1;
            unpack2(q2[e], q0, q1);
            unpack2(pneg, pn0, pn1);
            out[idx] = make_float4(q0, pn0, q1, pn1);
        }
    }
}

extern "C" void kernel_launch(void* const* d_in, const int* in_sizes, int n_in,
                              void* d_out, int out_size)
{
    const float4* x     = (const float4*)d_in[0];
    const float*  act_w = (const float*)d_in[1];
    const float*  bias_b= (const float*)d_in[2];
    const float*  lin_w = (const float*)d_in[3];
    float4* out = (float4*)d_out;

    int n4 = in_sizes[0] / 4;          // float4 count

    int per_block = TPB * PAIRS;
    int blocks = (n4 + per_block - 1) / per_block;
    sympnet_kernel<<<blocks, TPB>>>(x, act_w, bias_b, lin_w, out, n4);
}

// round 4
// speedup vs baseline: 1.0740x; 1.0740x over previous
#include <cuda_runtime.h>

#define N_LAYERS 32
#define N_SUB    8
#define TPB      256
#define PAIRS    2          // f32x2 chains per thread = 4 elements/thread

typedef unsigned long long u64;

__device__ __forceinline__ u64 pack2(float a, float b) {
    u64 r;
    asm("mov.b64 %0, {%1, %2};" : "=l"(r) : "f"(a), "f"(b));
    return r;
}
__device__ __forceinline__ void unpack2(u64 v, float& a, float& b) {
    asm("mov.b64 {%0, %1}, %2;" : "=f"(a), "=f"(b) : "l"(v));
}
__device__ __forceinline__ u64 fma2(u64 a, u64 b, u64 c) {
    u64 d;
    asm("fma.rn.f32x2 %0, %1, %2, %3;" : "=l"(d) : "l"(a), "l"(b), "l"(c));
    return d;
}

// tanh of both f32 lanes via one MUFU f16x2 op (1 F2FP + 1 MUFU + 2 F2F).
__device__ __forceinline__ u64 tanh2(u64 x) {
    u64 r;
    asm("{\n\t"
        ".reg .f32 lo, hi, tlo, thi;\n\t"
        ".reg .b32 h;\n\t"
        ".reg .b16 ha, hb;\n\t"
        "mov.b64 {lo, hi}, %1;\n\t"
        "cvt.rn.f16x2.f32 h, hi, lo;\n\t"
        "tanh.approx.f16x2 h, h;\n\t"
        "mov.b32 {ha, hb}, h;\n\t"
        "cvt.f32.f16 tlo, ha;\n\t"
        "cvt.f32.f16 thi, hb;\n\t"
        "mov.b64 %0, {tlo, thi};\n\t"
        "}" : "=l"(r) : "l"(x));
    return r;
}

#define SIGNMASK2 0x8000000080000000ULL

__global__ __launch_bounds__(TPB, 7)
void sympnet_kernel(const float4* __restrict__ x,
                    const float*  __restrict__ act_w,
                    const float*  __restrict__ bias_b,
                    const float*  __restrict__ lin_w,
                    float4*       __restrict__ out,
                    int n4)
{
    // Layer constants, duplicated into both f32x2 lanes, packed for LDS.128:
    // s_f[i] = { {aw,m00}, {m01,c0}, {m10,m11}, {c1,pad} }
    // s_r[i] = { {naw,u00}, {u01,d0}, {u10,u11}, {d1,pad} }
    __shared__ ulonglong2 s_f[N_LAYERS][4];
    __shared__ ulonglong2 s_r[N_LAYERS][4];

    const int t = threadIdx.x;

    if (t < N_LAYERS) {
        const int i = t;
        float m00 = 1.f, m01 = 0.f, m10 = 0.f, m11 = 1.f;
        float c0 = bias_b[2 * i + 0];
        float c1 = bias_b[2 * i + 1];
        #pragma unroll
        for (int j = 0; j < N_SUB; ++j) {
            float w = lin_w[i * N_SUB + j];
            if ((j & 1) == 0) {          // q += w*p
                m00 = fmaf(w, m10, m00);
                m01 = fmaf(w, m11, m01);
                c0  = fmaf(w, c1,  c0);
            } else {                      // p += w*q
                m10 = fmaf(w, m00, m10);
                m11 = fmaf(w, m01, m11);
                c1  = fmaf(w, c0,  c1);
            }
        }
        float aw = act_w[i];
        s_f[i][0] = make_ulonglong2(pack2(aw,  aw),  pack2(m00, m00));
        s_f[i][1] = make_ulonglong2(pack2(m01, m01), pack2(c0,  c0));
        s_f[i][2] = make_ulonglong2(pack2(m10, m10), pack2(m11, m11));
        s_f[i][3] = make_ulonglong2(pack2(c1,  c1),  0ULL);
    } else if (t < 2 * N_LAYERS) {
        const int i = t - N_LAYERS;
        float u00 = 1.f, u01 = 0.f, u10 = 0.f, u11 = 1.f;
        float d0 = 0.f, d1 = 0.f;
        #pragma unroll
        for (int j = N_SUB - 1; j >= 0; --j) {
            float w = lin_w[i * N_SUB + j];
            if ((j & 1) == 0) {          // q -= w*p
                u00 = fmaf(-w, u10, u00);
                u01 = fmaf(-w, u11, u01);
                d0  = fmaf(-w, d1,  d0);
            } else {                      // p -= w*q
                u10 = fmaf(-w, u00, u10);
                u11 = fmaf(-w, u01, u11);
                d1  = fmaf(-w, d0,  d1);
            }
        }
        d0 -= bias_b[2 * i + 0];
        d1 -= bias_b[2 * i + 1];
        float naw = -act_w[i];
        s_r[i][0] = make_ulonglong2(pack2(naw, naw), pack2(u00, u00));
        s_r[i][1] = make_ulonglong2(pack2(u01, u01), pack2(d0,  d0));
        s_r[i][2] = make_ulonglong2(pack2(u10, u10), pack2(u11, u11));
        s_r[i][3] = make_ulonglong2(pack2(d1,  d1),  0ULL);
    }
    __syncthreads();

    const int base = blockIdx.x * (TPB * PAIRS) + t;

    u64 q2[PAIRS], p2[PAIRS];
    #pragma unroll
    for (int e = 0; e < PAIRS; ++e) {
        int idx = base + e * TPB;
        if (idx < n4) {
            float4 v = x[idx];            // {q0, p0, q1, p1}
            q2[e] = pack2(v.x, v.z);
            p2[e] = pack2(v.y, v.w);
        } else {
            q2[e] = 0ULL; p2[e] = 0ULL;
        }
    }

    // ---------------- forward chain ----------------
    #pragma unroll 1
    for (int i = 0; i < N_LAYERS; i += 2) {
        {   // even layer: q += aw*tanh(p), then affine
            ulonglong2 v0 = s_f[i][0];
            ulonglong2 v1 = s_f[i][1];
            ulonglong2 v2 = s_f[i][2];
            ulonglong2 v3 = s_f[i][3];
            #pragma unroll
            for (int e = 0; e < PAIRS; ++e) {
                u64 tq = fma2(v0.x, tanh2(p2[e]), q2[e]);        // q + aw*tanh(p)
                u64 nq = fma2(v0.y, tq, fma2(v1.x, p2[e], v1.y)); // m00*q' + m01*p + c0
                u64 np = fma2(v2.x, tq, fma2(v2.y, p2[e], v3.x)); // m10*q' + m11*p + c1
                q2[e] = nq; p2[e] = np;
            }
        }
        {   // odd layer: p += aw*tanh(q), then affine
            ulonglong2 v0 = s_f[i + 1][0];
            ulonglong2 v1 = s_f[i + 1][1];
            ulonglong2 v2 = s_f[i + 1][2];
            ulonglong2 v3 = s_f[i + 1][3];
            #pragma unroll
            for (int e = 0; e < PAIRS; ++e) {
                u64 tp = fma2(v0.x, tanh2(q2[e]), p2[e]);
                u64 nq = fma2(v0.y, q2[e], fma2(v1.x, tp, v1.y));
                u64 np = fma2(v2.x, q2[e], fma2(v2.y, tp, v3.x));
                q2[e] = nq; p2[e] = np;
            }
        }
    }

    // time reversal: p = -p
    #pragma unroll
    for (int e = 0; e < PAIRS; ++e) p2[e] ^= SIGNMASK2;

    // ---------------- inverse chain ----------------
    #pragma unroll 1
    for (int i = N_LAYERS - 2; i >= 0; i -= 2) {
        {   // odd layer i+1: inverse affine, then p -= aw*tanh(q)
            ulonglong2 v0 = s_r[i + 1][0];
            ulonglong2 v1 = s_r[i + 1][1];
            ulonglong2 v2 = s_r[i + 1][2];
            ulonglong2 v3 = s_r[i + 1][3];
            #pragma unroll
            for (int e = 0; e < PAIRS; ++e) {
                u64 nq = fma2(v0.y, q2[e], fma2(v1.x, p2[e], v1.y)); // u00*q + u01*p + d0
                u64 np = fma2(v2.x, q2[e], fma2(v2.y, p2[e], v3.x)); // u10*q + u11*p + d1
                q2[e] = nq;
                p2[e] = fma2(v0.x, tanh2(nq), np);                   // p - aw*tanh(q)
            }
        }
        {   // even layer i: inverse affine, then q -= aw*tanh(p)
            ulonglong2 v0 = s_r[i][0];
            ulonglong2 v1 = s_r[i][1];
            ulonglong2 v2 = s_r[i][2];
            ulonglong2 v3 = s_r[i][3];
            #pragma unroll
            for (int e = 0; e < PAIRS; ++e) {
                u64 nq = fma2(v0.y, q2[e], fma2(v1.x, p2[e], v1.y));
                u64 np = fma2(v2.x, q2[e], fma2(v2.y, p2[e], v3.x));
                p2[e] = np;
                q2[e] = fma2(v0.x, tanh2(np), nq);
            }
        }
    }

    // output: (q, -p)
    #pragma unroll
    for (int e = 0; e < PAIRS; ++e) {
        int idx = base + e * TPB;
        if (idx < n4) {
            u64 pneg = p2[e] ^ SIGNMASK2;
            float q0, q1, pn0, pn1;
            unpack2(q2[e], q0, q1);
            unpack2(pneg, pn0, pn1);
            out[idx] = make_float4(q0, pn0, q1, pn1);
        }
    }
}

extern "C" void kernel_launch(void* const* d_in, const int* in_sizes, int n_in,
                              void* d_out, int out_size)
{
    const float4* x     = (const float4*)d_in[0];
    const float*  act_w = (const float*)d_in[1];
    const float*  bias_b= (const float*)d_in[2];
    const float*  lin_w = (const float*)d_in[3];
    float4* out = (float4*)d_out;

    int n4 = in_sizes[0] / 4;          // float4 count

    int per_block = TPB * PAIRS;
    int blocks = (n4 + per_block - 1) / per_block;
    sympnet_kernel<<<blocks, TPB>>>(x, act_w, bias_b, lin_w, out, n4);
}

// round 5
// speedup vs baseline: 1.0808x; 1.0063x over previous
#include <cuda_runtime.h>

#define N_LAYERS 32
#define N_SUB    8
#define TPB      256
#define PAIRS    4          // f32x2 chains per thread = 8 elements/thread

typedef unsigned long long u64;

__device__ __forceinline__ u64 pack2(float a, float b) {
    u64 r;
    asm("mov.b64 %0, {%1, %2};" : "=l"(r) : "f"(a), "f"(b));
    return r;
}
__device__ __forceinline__ void unpack2(u64 v, float& a, float& b) {
    asm("mov.b64 {%0, %1}, %2;" : "=f"(a), "=f"(b) : "l"(v));
}
__device__ __forceinline__ u64 fma2(u64 a, u64 b, u64 c) {
    u64 d;
    asm("fma.rn.f32x2 %0, %1, %2, %3;" : "=l"(d) : "l"(a), "l"(b), "l"(c));
    return d;
}

// tanh of both f32 lanes via one MUFU f16x2 op (1 F2FP + 1 MUFU + 2 F2F).
__device__ __forceinline__ u64 tanh2(u64 x) {
    u64 r;
    asm("{\n\t"
        ".reg .f32 lo, hi, tlo, thi;\n\t"
        ".reg .b32 h;\n\t"
        ".reg .b16 ha, hb;\n\t"
        "mov.b64 {lo, hi}, %1;\n\t"
        "cvt.rn.f16x2.f32 h, hi, lo;\n\t"
        "tanh.approx.f16x2 h, h;\n\t"
        "mov.b32 {ha, hb}, h;\n\t"
        "cvt.f32.f16 tlo, ha;\n\t"
        "cvt.f32.f16 thi, hb;\n\t"
        "mov.b64 %0, {tlo, thi};\n\t"
        "}" : "=l"(r) : "l"(x));
    return r;
}

#define SIGNMASK2 0x8000000080000000ULL

__global__ __launch_bounds__(TPB, 6)
void sympnet_kernel(const float4* __restrict__ x,
                    const float*  __restrict__ act_w,
                    const float*  __restrict__ bias_b,
                    const float*  __restrict__ lin_w,
                    float4*       __restrict__ out,
                    int n4)
{
    // Layer constants, duplicated into both f32x2 lanes, packed for LDS.128:
    // s_f[i] = { {aw,m00}, {m01,c0}, {m10,m11}, {c1,pad} }
    // s_r[i] = { {naw,u00}, {u01,d0}, {u10,u11}, {d1,pad} }
    __shared__ ulonglong2 s_f[N_LAYERS][4];
    __shared__ ulonglong2 s_r[N_LAYERS][4];

    const int t = threadIdx.x;

    if (t < N_LAYERS) {
        const int i = t;
        float m00 = 1.f, m01 = 0.f, m10 = 0.f, m11 = 1.f;
        float c0 = bias_b[2 * i + 0];
        float c1 = bias_b[2 * i + 1];
        #pragma unroll
        for (int j = 0; j < N_SUB; ++j) {
            float w = lin_w[i * N_SUB + j];
            if ((j & 1) == 0) {          // q += w*p
                m00 = fmaf(w, m10, m00);
                m01 = fmaf(w, m11, m01);
                c0  = fmaf(w, c1,  c0);
            } else {                      // p += w*q
                m10 = fmaf(w, m00, m10);
                m11 = fmaf(w, m01, m11);
                c1  = fmaf(w, c0,  c1);
            }
        }
        float aw = act_w[i];
        s_f[i][0] = make_ulonglong2(pack2(aw,  aw),  pack2(m00, m00));
        s_f[i][1] = make_ulonglong2(pack2(m01, m01), pack2(c0,  c0));
        s_f[i][2] = make_ulonglong2(pack2(m10, m10), pack2(m11, m11));
        s_f[i][3] = make_ulonglong2(pack2(c1,  c1),  0ULL);
    } else if (t < 2 * N_LAYERS) {
        const int i = t - N_LAYERS;
        float u00 = 1.f, u01 = 0.f, u10 = 0.f, u11 = 1.f;
        float d0 = 0.f, d1 = 0.f;
        #pragma unroll
        for (int j = N_SUB - 1; j >= 0; --j) {
            float w = lin_w[i * N_SUB + j];
            if ((j & 1) == 0) {          // q -= w*p
                u00 = fmaf(-w, u10, u00);
                u01 = fmaf(-w, u11, u01);
                d0  = fmaf(-w, d1,  d0);
            } else {                      // p -= w*q
                u10 = fmaf(-w, u00, u10);
                u11 = fmaf(-w, u01, u11);
                d1  = fmaf(-w, d0,  d1);
            }
        }
        d0 -= bias_b[2 * i + 0];
        d1 -= bias_b[2 * i + 1];
        float naw = -act_w[i];
        s_r[i][0] = make_ulonglong2(pack2(naw, naw), pack2(u00, u00));
        s_r[i][1] = make_ulonglong2(pack2(u01, u01), pack2(d0,  d0));
        s_r[i][2] = make_ulonglong2(pack2(u10, u10), pack2(u11, u11));
        s_r[i][3] = make_ulonglong2(pack2(d1,  d1),  0ULL);
    }
    __syncthreads();

    const int base = blockIdx.x * (TPB * PAIRS) + t;

    u64 q2[PAIRS], p2[PAIRS];
    #pragma unroll
    for (int e = 0; e < PAIRS; ++e) {
        int idx = base + e * TPB;
        if (idx < n4) {
            float4 v = x[idx];            // {q0, p0, q1, p1}
            q2[e] = pack2(v.x, v.z);
            p2[e] = pack2(v.y, v.w);
        } else {
            q2[e] = 0ULL; p2[e] = 0ULL;
        }
    }

    // ---------------- forward chain ----------------
    #pragma unroll 1
    for (int i = 0; i < N_LAYERS; i += 2) {
        {   // even layer: q += aw*tanh(p), then affine
            ulonglong2 v0 = s_f[i][0];
            ulonglong2 v1 = s_f[i][1];
            ulonglong2 v2 = s_f[i][2];
            ulonglong2 v3 = s_f[i][3];
            #pragma unroll
            for (int e = 0; e < PAIRS; ++e) {
                u64 tq = fma2(v0.x, tanh2(p2[e]), q2[e]);         // q + aw*tanh(p)
                u64 nq = fma2(v0.y, tq, fma2(v1.x, p2[e], v1.y)); // m00*q' + m01*p + c0
                u64 np = fma2(v2.x, tq, fma2(v2.y, p2[e], v3.x)); // m10*q' + m11*p + c1
                q2[e] = nq; p2[e] = np;
            }
        }
        {   // odd layer: p += aw*tanh(q), then affine
            ulonglong2 v0 = s_f[i + 1][0];
            ulonglong2 v1 = s_f[i + 1][1];
            ulonglong2 v2 = s_f[i + 1][2];
            ulonglong2 v3 = s_f[i + 1][3];
            #pragma unroll
            for (int e = 0; e < PAIRS; ++e) {
                u64 tp = fma2(v0.x, tanh2(q2[e]), p2[e]);
                u64 nq = fma2(v0.y, q2[e], fma2(v1.x, tp, v1.y));
                u64 np = fma2(v2.x, q2[e], fma2(v2.y, tp, v3.x));
                q2[e] = nq; p2[e] = np;
            }
        }
    }

    // time reversal: p = -p
    #pragma unroll
    for (int e = 0; e < PAIRS; ++e) p2[e] ^= SIGNMASK2;

    // ---------------- inverse chain ----------------
    #pragma unroll 1
    for (int i = N_LAYERS - 2; i >= 0; i -= 2) {
        {   // odd layer i+1: inverse affine, then p -= aw*tanh(q)
            ulonglong2 v0 = s_r[i + 1][0];
            ulonglong2 v1 = s_r[i + 1][1];
            ulonglong2 v2 = s_r[i + 1][2];
            ulonglong2 v3 = s_r[i + 1][3];
            #pragma unroll
            for (int e = 0; e < PAIRS; ++e) {
                u64 nq = fma2(v0.y, q2[e], fma2(v1.x, p2[e], v1.y)); // u00*q + u01*p + d0
                u64 np = fma2(v2.x, q2[e], fma2(v2.y, p2[e], v3.x)); // u10*q + u11*p + d1
                q2[e] = nq;
                p2[e] = fma2(v0.x, tanh2(nq), np);                   // p - aw*tanh(q)
            }
        }
        {   // even layer i: inverse affine, then q -= aw*tanh(p)
            ulonglong2 v0 = s_r[i][0];
            ulonglong2 v1 = s_r[i][1];
            ulonglong2 v2 = s_r[i][2];
            ulonglong2 v3 = s_r[i][3];
            #pragma unroll
            for (int e = 0; e < PAIRS; ++e) {
                u64 nq = fma2(v0.y, q2[e], fma2(v1.x, p2[e], v1.y));
                u64 np = fma2(v2.x, q2[e], fma2(v2.y, p2[e], v3.x));
                p2[e] = np;
                q2[e] = fma2(v0.x, tanh2(np), nq);
            }
        }
    }

    // output: (q, -p)
    #pragma unroll
    for (int e = 0; e < PAIRS; ++e) {
        int idx = base + e * TPB;
        if (idx < n4) {
            u64 pneg = p2[e] ^ SIGNMASK2;
            float q0, q1, pn0, pn1;
            unpack2(q2[e], q0, q1);
            unpack2(pneg, pn0, pn1);
            out[idx] = make_float4(q0, pn0, q1, pn1);
        }
    }
}

extern "C" void kernel_launch(void* const* d_in, const int* in_sizes, int n_in,
                              void* d_out, int out_size)
{
    const float4* x     = (const float4*)d_in[0];
    const float*  act_w = (const float*)d_in[1];
    const float*  bias_b= (const float*)d_in[2];
    const float*  lin_w = (const float*)d_in[3];
    float4* out = (float4*)d_out;

    int n4 = in_sizes[0] / 4;          // float4 count

    int per_block = TPB * PAIRS;
    int blocks = (n4 + per_block - 1) / per_block;
    sympnet_kernel<<<blocks, TPB>>>(x, act_w, bias_b, lin_w, out, n4);
}

// round 6
// speedup vs baseline: 1.2484x; 1.1550x over previous
#include <cuda_runtime.h>

#define N_LAYERS 32
#define N_BLK    16          // fused 2-layer blocks per chain
#define N_SUB    8
#define TPB      256
#define EPT      4

__device__ __forceinline__ float tanh_fast(float x) {
    float y;
    asm("tanh.approx.f32 %0, %1;" : "=f"(y) : "f"(x));
    return y;
}

// Compose layer i's (bias then 8 shears) into forward affine v' = M v + c.
__device__ __forceinline__ void compose_fwd(const float* bias_b, const float* lin_w,
                                            int i, float M[4], float c[2]) {
    float m00 = 1.f, m01 = 0.f, m10 = 0.f, m11 = 1.f;
    float c0 = bias_b[2 * i + 0];
    float c1 = bias_b[2 * i + 1];
    #pragma unroll
    for (int j = 0; j < N_SUB; ++j) {
        float w = lin_w[i * N_SUB + j];
        if ((j & 1) == 0) {          // q += w*p
            m00 = fmaf(w, m10, m00);
            m01 = fmaf(w, m11, m01);
            c0  = fmaf(w, c1,  c0);
        } else {                      // p += w*q
            m10 = fmaf(w, m00, m10);
            m11 = fmaf(w, m01, m11);
            c1  = fmaf(w, c0,  c1);
        }
    }
    M[0] = m00; M[1] = m01; M[2] = m10; M[3] = m11;
    c[0] = c0;  c[1] = c1;
}

// Inverse affine of layer i: v = U w + d (reversed negated shears; d = -bias).
__device__ __forceinline__ void compose_inv(const float* bias_b, const float* lin_w,
                                            int i, float U[4], float d[2]) {
    float u00 = 1.f, u01 = 0.f, u10 = 0.f, u11 = 1.f;
    #pragma unroll
    for (int j = N_SUB - 1; j >= 0; --j) {
        float w = lin_w[i * N_SUB + j];
        if ((j & 1) == 0) {          // q -= w*p
            u00 = fmaf(-w, u10, u00);
            u01 = fmaf(-w, u11, u01);
        } else {                      // p -= w*q
            u10 = fmaf(-w, u00, u10);
            u11 = fmaf(-w, u01, u11);
        }
    }
    U[0] = u00; U[1] = u01; U[2] = u10; U[3] = u11;
    d[0] = -bias_b[2 * i + 0];
    d[1] = -bias_b[2 * i + 1];
}

__global__ __launch_bounds__(TPB)
void sympnet_kernel(const float2* __restrict__ x,
                    const float*  __restrict__ act_w,
                    const float*  __restrict__ bias_b,
                    const float*  __restrict__ lin_w,
                    float2*       __restrict__ out,
                    int n)
{
    // Fused 2-layer block constants (3 x float4 each):
    // fwd[k]: [0]={a_e, Me00, Me01, ce0}  [1]={A00,A01,b0,ah0}  [2]={A10,A11,b1,ah1}
    // inv[k]: [0]={Uo00, Uo01, do0, -a_e} [1]={B00,B01,e0,ch0}  [2]={B10,B11,e1,ch1}
    __shared__ float4 s_fb[N_BLK][3];
    __shared__ float4 s_ib[N_BLK][3];

    const int t = threadIdx.x;

    if (t < N_BLK) {
        const int k = t, i = 2 * k;
        float Me[4], ce[2], Mo[4], co[2];
        compose_fwd(bias_b, lin_w, i,     Me, ce);
        compose_fwd(bias_b, lin_w, i + 1, Mo, co);
        float a_e = act_w[i], a_o = act_w[i + 1];
        // A = Mo * Me ; b = Mo*ce + co ; ah = a_o * (Mo col-p)
        float A00 = Mo[0] * Me[0] + Mo[1] * Me[2];
        float A01 = Mo[0] * Me[1] + Mo[1] * Me[3];
        float A10 = Mo[2] * Me[0] + Mo[3] * Me[2];
        float A11 = Mo[2] * Me[1] + Mo[3] * Me[3];
        float b0  = Mo[0] * ce[0] + Mo[1] * ce[1] + co[0];
        float b1  = Mo[2] * ce[0] + Mo[3] * ce[1] + co[1];
        float ah0 = a_o * Mo[1];
        float ah1 = a_o * Mo[3];
        s_fb[k][0] = make_float4(a_e, Me[0], Me[1], ce[0]);
        s_fb[k][1] = make_float4(A00, A01, b0, ah0);
        s_fb[k][2] = make_float4(A10, A11, b1, ah1);
    } else if (t < 2 * N_BLK) {
        const int k = t - N_BLK, i = 2 * k;
        float Ue[4], de[2], Uo[4], dd[2];
        compose_inv(bias_b, lin_w, i,     Ue, de);
        compose_inv(bias_b, lin_w, i + 1, Uo, dd);
        float a_e = act_w[i], a_o = act_w[i + 1];
        // B = Ue * Uo ; e = Ue*do + de ; ch = -a_o * (Ue col-p)
        float B00 = Ue[0] * Uo[0] + Ue[1] * Uo[2];
        float B01 = Ue[0] * Uo[1] + Ue[1] * Uo[3];
        float B10 = Ue[2] * Uo[0] + Ue[3] * Uo[2];
        float B11 = Ue[2] * Uo[1] + Ue[3] * Uo[3];
        float e0  = Ue[0] * dd[0] + Ue[1] * dd[1] + de[0];
        float e1  = Ue[2] * dd[0] + Ue[3] * dd[1] + de[1];
        float ch0 = -a_o * Ue[1];
        float ch1 = -a_o * Ue[3];
        s_ib[k][0] = make_float4(Uo[0], Uo[1], dd[0], -a_e);
        s_ib[k][1] = make_float4(B00, B01, e0, ch0);
        s_ib[k][2] = make_float4(B10, B11, e1, ch1);
    }
    __syncthreads();

    const int base = blockIdx.x * (TPB * EPT) + t;

    float q[EPT], p[EPT];
    #pragma unroll
    for (int e = 0; e < EPT; ++e) {
        int idx = base + e * TPB;
        if (idx < n) {
            float2 v = x[idx];
            q[e] = v.x; p[e] = v.y;
        } else {
            q[e] = 0.f; p[e] = 0.f;
        }
    }

    // ---------------- forward chain: 16 fused blocks ----------------
    #pragma unroll 1
    for (int k = 0; k < N_BLK; ++k) {
        float4 fa = s_fb[k][0];
        float4 fb = s_fb[k][1];
        float4 fc = s_fb[k][2];
        #pragma unroll
        for (int e = 0; e < EPT; ++e) {
            float t1 = tanh_fast(p[e]);
            float q1 = fmaf(fa.x, t1, q[e]);                        // q + a_e*tanh(p)
            float q2 = fmaf(fa.y, q1, fmaf(fa.z, p[e], fa.w));      // row0 of Me affine
            float t2 = tanh_fast(q2);
            float nq = fmaf(fb.w, t2, fmaf(fb.x, q1, fmaf(fb.y, p[e], fb.z)));
            float np = fmaf(fc.w, t2, fmaf(fc.x, q1, fmaf(fc.y, p[e], fc.z)));
            q[e] = nq; p[e] = np;
        }
    }

    // time reversal
    #pragma unroll
    for (int e = 0; e < EPT; ++e) p[e] = -p[e];

    // ---------------- inverse chain: 16 fused blocks (reverse order) ----------------
    #pragma unroll 1
    for (int k = N_BLK - 1; k >= 0; --k) {
        float4 ia = s_ib[k][0];
        float4 ib = s_ib[k][1];
        float4 ic = s_ib[k][2];
        #pragma unroll
        for (int e = 0; e < EPT; ++e) {
            float qp = fmaf(ia.x, q[e], fmaf(ia.y, p[e], ia.z));    // q' = row0 of Uo affine
            float t2 = tanh_fast(qp);
            float nq = fmaf(ib.w, t2, fmaf(ib.x, q[e], fmaf(ib.y, p[e], ib.z)));
            float np = fmaf(ic.w, t2, fmaf(ic.x, q[e], fmaf(ic.y, p[e], ic.z)));
            q[e] = fmaf(ia.w, tanh_fast(np), nq);                   // q'' - a_e*tanh(p'')
            p[e] = np;
        }
    }

    #pragma unroll
    for (int e = 0; e < EPT; ++e) {
        int idx = base + e * TPB;
        if (idx < n) {
            out[idx] = make_float2(q[e], -p[e]);
        }
    }
}

extern "C" void kernel_launch(void* const* d_in, const int* in_sizes, int n_in,
                              void* d_out, int out_size)
{
    const float2* x     = (const float2*)d_in[0];
    const float*  act_w = (const float*)d_in[1];
    const float*  bias_b= (const float*)d_in[2];
    const float*  lin_w = (const float*)d_in[3];
    float2* out = (float2*)d_out;

    int n = in_sizes[0] / 2;   // number of (q,p) pairs

    int per_block = TPB * EPT;
    int blocks = (n + per_block - 1) / per_block;
    sympnet_kernel<<<blocks, TPB>>>(x, act_w, bias_b, lin_w, out, n);
}

// round 7
// speedup vs baseline: 1.2990x; 1.0405x over previous
#include <cuda_runtime.h>

#define N_LAYERS 32
#define N_BLK    16          // fused 2-layer blocks per chain
#define N_SUB    8
#define TPB      256
#define EPT      4

__device__ __forceinline__ float tanh_fast(float x) {
    float y;
    asm("tanh.approx.f32 %0, %1;" : "=f"(y) : "f"(x));
    return y;
}

// Compose layer i's (bias then 8 shears) into forward affine v' = M v + c.
__device__ __forceinline__ void compose_fwd(const float* bias_b, const float* lin_w,
                                            int i, float M[4], float c[2]) {
    float m00 = 1.f, m01 = 0.f, m10 = 0.f, m11 = 1.f;
    float c0 = bias_b[2 * i + 0];
    float c1 = bias_b[2 * i + 1];
    #pragma unroll
    for (int j = 0; j < N_SUB; ++j) {
        float w = lin_w[i * N_SUB + j];
        if ((j & 1) == 0) {          // q += w*p
            m00 = fmaf(w, m10, m00);
            m01 = fmaf(w, m11, m01);
            c0  = fmaf(w, c1,  c0);
        } else {                      // p += w*q
            m10 = fmaf(w, m00, m10);
            m11 = fmaf(w, m01, m11);
            c1  = fmaf(w, c0,  c1);
        }
    }
    M[0] = m00; M[1] = m01; M[2] = m10; M[3] = m11;
    c[0] = c0;  c[1] = c1;
}

// Inverse affine of layer i: v = U w + d (reversed negated shears; d = -bias).
__device__ __forceinline__ void compose_inv(const float* bias_b, const float* lin_w,
                                            int i, float U[4], float d[2]) {
    float u00 = 1.f, u01 = 0.f, u10 = 0.f, u11 = 1.f;
    #pragma unroll
    for (int j = N_SUB - 1; j >= 0; --j) {
        float w = lin_w[i * N_SUB + j];
        if ((j & 1) == 0) {          // q -= w*p
            u00 = fmaf(-w, u10, u00);
            u01 = fmaf(-w, u11, u01);
        } else {                      // p -= w*q
            u10 = fmaf(-w, u00, u10);
            u11 = fmaf(-w, u01, u11);
        }
    }
    U[0] = u00; U[1] = u01; U[2] = u10; U[3] = u11;
    d[0] = -bias_b[2 * i + 0];
    d[1] = -bias_b[2 * i + 1];
}

__global__ __launch_bounds__(TPB)
void sympnet_kernel(const float2* __restrict__ x,
                    const float*  __restrict__ act_w,
                    const float*  __restrict__ bias_b,
                    const float*  __restrict__ lin_w,
                    float2*       __restrict__ out,
                    int n)
{
    // Fused 2-layer block constants (3 x float4 each):
    // fwd[k]: [0]={a_e, Me00, Me01, ce0}  [1]={A00,A01,b0,ah0}  [2]={A10,A11,b1,ah1}
    // inv[k]: [0]={Uo00, Uo01, do0, -a_e} [1]={B00,B01,e0,ch0}  [2]={B10,B11,e1,ch1}
    __shared__ float4 s_fb[N_BLK][3];
    __shared__ float4 s_ib[N_BLK][3];

    const int t = threadIdx.x;

    if (t < N_BLK) {
        const int k = t, i = 2 * k;
        float Me[4], ce[2], Mo[4], co[2];
        compose_fwd(bias_b, lin_w, i,     Me, ce);
        compose_fwd(bias_b, lin_w, i + 1, Mo, co);
        float a_e = act_w[i], a_o = act_w[i + 1];
        // A = Mo * Me ; b = Mo*ce + co ; ah = a_o * (Mo col-p)
        float A00 = Mo[0] * Me[0] + Mo[1] * Me[2];
        float A01 = Mo[0] * Me[1] + Mo[1] * Me[3];
        float A10 = Mo[2] * Me[0] + Mo[3] * Me[2];
        float A11 = Mo[2] * Me[1] + Mo[3] * Me[3];
        float b0  = Mo[0] * ce[0] + Mo[1] * ce[1] + co[0];
        float b1  = Mo[2] * ce[0] + Mo[3] * ce[1] + co[1];
        float ah0 = a_o * Mo[1];
        float ah1 = a_o * Mo[3];
        s_fb[k][0] = make_float4(a_e, Me[0], Me[1], ce[0]);
        s_fb[k][1] = make_float4(A00, A01, b0, ah0);
        s_fb[k][2] = make_float4(A10, A11, b1, ah1);
    } else if (t < 2 * N_BLK) {
        const int k = t - N_BLK, i = 2 * k;
        float Ue[4], de[2], Uo[4], dd[2];
        compose_inv(bias_b, lin_w, i,     Ue, de);
        compose_inv(bias_b, lin_w, i + 1, Uo, dd);
        float a_e = act_w[i], a_o = act_w[i + 1];
        // B = Ue * Uo ; e = Ue*do + de ; ch = -a_o * (Ue col-p)
        float B00 = Ue[0] * Uo[0] + Ue[1] * Uo[2];
        float B01 = Ue[0] * Uo[1] + Ue[1] * Uo[3];
        float B10 = Ue[2] * Uo[0] + Ue[3] * Uo[2];
        float B11 = Ue[2] * Uo[1] + Ue[3] * Uo[3];
        float e0  = Ue[0] * dd[0] + Ue[1] * dd[1] + de[0];
        float e1  = Ue[2] * dd[0] + Ue[3] * dd[1] + de[1];
        float ch0 = -a_o * Ue[1];
        float ch1 = -a_o * Ue[3];
        s_ib[k][0] = make_float4(Uo[0], Uo[1], dd[0], -a_e);
        s_ib[k][1] = make_float4(B00, B01, e0, ch0);
        s_ib[k][2] = make_float4(B10, B11, e1, ch1);
    }
    __syncthreads();

    const int base = blockIdx.x * (TPB * EPT) + t;

    float q[EPT], p[EPT];
    #pragma unroll
    for (int e = 0; e < EPT; ++e) {
        int idx = base + e * TPB;
        if (idx < n) {
            float2 v = x[idx];
            q[e] = v.x; p[e] = v.y;
        } else {
            q[e] = 0.f; p[e] = 0.f;
        }
    }

    // ---------------- forward chain: 16 fused blocks, fully unrolled ----------------
    #pragma unroll
    for (int k = 0; k < N_BLK; ++k) {
        float4 fa = s_fb[k][0];
        float4 fb = s_fb[k][1];
        float4 fc = s_fb[k][2];
        #pragma unroll
        for (int e = 0; e < EPT; ++e) {
            float t1 = tanh_fast(p[e]);
            float q1 = fmaf(fa.x, t1, q[e]);                        // q + a_e*tanh(p)
            float q2 = fmaf(fa.y, q1, fmaf(fa.z, p[e], fa.w));      // row0 of Me affine
            float t2 = tanh_fast(q2);
            float nq = fmaf(fb.w, t2, fmaf(fb.x, q1, fmaf(fb.y, p[e], fb.z)));
            float np = fmaf(fc.w, t2, fmaf(fc.x, q1, fmaf(fc.y, p[e], fc.z)));
            q[e] = nq; p[e] = np;
        }
    }

    // time reversal
    #pragma unroll
    for (int e = 0; e < EPT; ++e) p[e] = -p[e];

    // ---------------- inverse chain: 16 fused blocks, fully unrolled ----------------
    #pragma unroll
    for (int k = N_BLK - 1; k >= 0; --k) {
        float4 ia = s_ib[k][0];
        float4 ib = s_ib[k][1];
        float4 ic = s_ib[k][2];
        #pragma unroll
        for (int e = 0; e < EPT; ++e) {
            float qp = fmaf(ia.x, q[e], fmaf(ia.y, p[e], ia.z));    // q' = row0 of Uo affine
            float t2 = tanh_fast(qp);
            float nq = fmaf(ib.w, t2, fmaf(ib.x, q[e], fmaf(ib.y, p[e], ib.z)));
            float np = fmaf(ic.w, t2, fmaf(ic.x, q[e], fmaf(ic.y, p[e], ic.z)));
            q[e] = fmaf(ia.w, tanh_fast(np), nq);                   // q'' - a_e*tanh(p'')
            p[e] = np;
        }
    }

    #pragma unroll
    for (int e = 0; e < EPT; ++e) {
        int idx = base + e * TPB;
        if (idx < n) {
            out[idx] = make_float2(q[e], -p[e]);
        }
    }
}

extern "C" void kernel_launch(void* const* d_in, const int* in_sizes, int n_in,
                              void* d_out, int out_size)
{
    const float2* x     = (const float2*)d_in[0];
    const float*  act_w = (const float*)d_in[1];
    const float*  bias_b= (const float*)d_in[2];
    const float*  lin_w = (const float*)d_in[3];
    float2* out = (float2*)d_out;

    int n = in_sizes[0] / 2;   // number of (q,p) pairs

    int per_block = TPB * EPT;
    int blocks = (n + per_block - 1) / per_block;
    sympnet_kernel<<<blocks, TPB>>>(x, act_w, bias_b, lin_w, out, n);
}

// round 8
// speedup vs baseline: 1.3931x; 1.0725x over previous
#include <cuda_runtime.h>

#define N_LAYERS 32
#define N_BLK    16          // fused 2-layer blocks per chain
#define N_SUB    8
#define TPB      256
#define EPT      6

__device__ __forceinline__ float tanh_fast(float x) {
    float y;
    asm("tanh.approx.f32 %0, %1;" : "=f"(y) : "f"(x));
    return y;
}

// Compose layer i's (bias then 8 shears) into forward affine v' = M v + c.
__device__ __forceinline__ void compose_fwd(const float* bias_b, const float* lin_w,
                                            int i, float M[4], float c[2]) {
    float m00 = 1.f, m01 = 0.f, m10 = 0.f, m11 = 1.f;
    float c0 = bias_b[2 * i + 0];
    float c1 = bias_b[2 * i + 1];
    #pragma unroll
    for (int j = 0; j < N_SUB; ++j) {
        float w = lin_w[i * N_SUB + j];
        if ((j & 1) == 0) {          // q += w*p
            m00 = fmaf(w, m10, m00);
            m01 = fmaf(w, m11, m01);
            c0  = fmaf(w, c1,  c0);
        } else {                      // p += w*q
            m10 = fmaf(w, m00, m10);
            m11 = fmaf(w, m01, m11);
            c1  = fmaf(w, c0,  c1);
        }
    }
    M[0] = m00; M[1] = m01; M[2] = m10; M[3] = m11;
    c[0] = c0;  c[1] = c1;
}

// Inverse affine of layer i: v = U w + d (reversed negated shears; d = -bias).
__device__ __forceinline__ void compose_inv(const float* bias_b, const float* lin_w,
                                            int i, float U[4], float d[2]) {
    float u00 = 1.f, u01 = 0.f, u10 = 0.f, u11 = 1.f;
    #pragma unroll
    for (int j = N_SUB - 1; j >= 0; --j) {
        float w = lin_w[i * N_SUB + j];
        if ((j & 1) == 0) {          // q -= w*p
            u00 = fmaf(-w, u10, u00);
            u01 = fmaf(-w, u11, u01);
        } else {                      // p -= w*q
            u10 = fmaf(-w, u00, u10);
            u11 = fmaf(-w, u01, u11);
        }
    }
    U[0] = u00; U[1] = u01; U[2] = u10; U[3] = u11;
    d[0] = -bias_b[2 * i + 0];
    d[1] = -bias_b[2 * i + 1];
}

__global__ __launch_bounds__(TPB, 5)
void sympnet_kernel(const float2* __restrict__ x,
                    const float*  __restrict__ act_w,
                    const float*  __restrict__ bias_b,
                    const float*  __restrict__ lin_w,
                    float2*       __restrict__ out,
                    int n)
{
    // Fused 2-layer block constants (3 x float4 each):
    // fwd[k]: [0]={a_e, Me00, Me01, ce0}  [1]={A00,A01,b0,ah0}  [2]={A10,A11,b1,ah1}
    // inv[k]: [0]={Uo00, Uo01, do0, -a_e} [1]={B00,B01,e0,ch0}  [2]={B10,B11,e1,ch1}
    __shared__ float4 s_fb[N_BLK][3];
    __shared__ float4 s_ib[N_BLK][3];

    const int t = threadIdx.x;

    if (t < N_BLK) {
        const int k = t, i = 2 * k;
        float Me[4], ce[2], Mo[4], co[2];
        compose_fwd(bias_b, lin_w, i,     Me, ce);
        compose_fwd(bias_b, lin_w, i + 1, Mo, co);
        float a_e = act_w[i], a_o = act_w[i + 1];
        // A = Mo * Me ; b = Mo*ce + co ; ah = a_o * (Mo col-p)
        float A00 = Mo[0] * Me[0] + Mo[1] * Me[2];
        float A01 = Mo[0] * Me[1] + Mo[1] * Me[3];
        float A10 = Mo[2] * Me[0] + Mo[3] * Me[2];
        float A11 = Mo[2] * Me[1] + Mo[3] * Me[3];
        float b0  = Mo[0] * ce[0] + Mo[1] * ce[1] + co[0];
        float b1  = Mo[2] * ce[0] + Mo[3] * ce[1] + co[1];
        float ah0 = a_o * Mo[1];
        float ah1 = a_o * Mo[3];
        s_fb[k][0] = make_float4(a_e, Me[0], Me[1], ce[0]);
        s_fb[k][1] = make_float4(A00, A01, b0, ah0);
        s_fb[k][2] = make_float4(A10, A11, b1, ah1);
    } else if (t < 2 * N_BLK) {
        const int k = t - N_BLK, i = 2 * k;
        float Ue[4], de[2], Uo[4], dd[2];
        compose_inv(bias_b, lin_w, i,     Ue, de);
        compose_inv(bias_b, lin_w, i + 1, Uo, dd);
        float a_e = act_w[i], a_o = act_w[i + 1];
        // B = Ue * Uo ; e = Ue*do + de ; ch = -a_o * (Ue col-p)
        float B00 = Ue[0] * Uo[0] + Ue[1] * Uo[2];
        float B01 = Ue[0] * Uo[1] + Ue[1] * Uo[3];
        float B10 = Ue[2] * Uo[0] + Ue[3] * Uo[2];
        float B11 = Ue[2] * Uo[1] + Ue[3] * Uo[3];
        float e0  = Ue[0] * dd[0] + Ue[1] * dd[1] + de[0];
        float e1  = Ue[2] * dd[0] + Ue[3] * dd[1] + de[1];
        float ch0 = -a_o * Ue[1];
        float ch1 = -a_o * Ue[3];
        s_ib[k][0] = make_float4(Uo[0], Uo[1], dd[0], -a_e);
        s_ib[k][1] = make_float4(B00, B01, e0, ch0);
        s_ib[k][2] = make_float4(B10, B11, e1, ch1);
    }
    __syncthreads();

    const int base = blockIdx.x * (TPB * EPT) + t;

    float q[EPT], p[EPT];
    #pragma unroll
    for (int e = 0; e < EPT; ++e) {
        int idx = base + e * TPB;
        if (idx < n) {
            float2 v = x[idx];
            q[e] = v.x; p[e] = v.y;
        } else {
            q[e] = 0.f; p[e] = 0.f;
        }
    }

    // ---------------- forward chain: 16 fused blocks ----------------
    #pragma unroll 4
    for (int k = 0; k < N_BLK; ++k) {
        float4 fa = s_fb[k][0];
        float4 fb = s_fb[k][1];
        float4 fc = s_fb[k][2];
        #pragma unroll
        for (int e = 0; e < EPT; ++e) {
            float t1 = tanh_fast(p[e]);
            float q1 = fmaf(fa.x, t1, q[e]);                        // q + a_e*tanh(p)
            float q2 = fmaf(fa.y, q1, fmaf(fa.z, p[e], fa.w));      // row0 of Me affine
            float t2 = tanh_fast(q2);
            float nq = fmaf(fb.w, t2, fmaf(fb.x, q1, fmaf(fb.y, p[e], fb.z)));
            float np = fmaf(fc.w, t2, fmaf(fc.x, q1, fmaf(fc.y, p[e], fc.z)));
            q[e] = nq; p[e] = np;
        }
    }

    // time reversal
    #pragma unroll
    for (int e = 0; e < EPT; ++e) p[e] = -p[e];

    // ---------------- inverse chain: 16 fused blocks (reverse order) ----------------
    #pragma unroll 4
    for (int k = N_BLK - 1; k >= 0; --k) {
        float4 ia = s_ib[k][0];
        float4 ib = s_ib[k][1];
        float4 ic = s_ib[k][2];
        #pragma unroll
        for (int e = 0; e < EPT; ++e) {
            float qp = fmaf(ia.x, q[e], fmaf(ia.y, p[e], ia.z));    // q' = row0 of Uo affine
            float t2 = tanh_fast(qp);
            float nq = fmaf(ib.w, t2, fmaf(ib.x, q[e], fmaf(ib.y, p[e], ib.z)));
            float np = fmaf(ic.w, t2, fmaf(ic.x, q[e], fmaf(ic.y, p[e], ic.z)));
            q[e] = fmaf(ia.w, tanh_fast(np), nq);                   // q'' - a_e*tanh(p'')
            p[e] = np;
        }
    }

    #pragma unroll
    for (int e = 0; e < EPT; ++e) {
        int idx = base + e * TPB;
        if (idx < n) {
            out[idx] = make_float2(q[e], -p[e]);
        }
    }
}

extern "C" void kernel_launch(void* const* d_in, const int* in_sizes, int n_in,
                              void* d_out, int out_size)
{
    const float2* x     = (const float2*)d_in[0];
    const float*  act_w = (const float*)d_in[1];
    const float*  bias_b= (const float*)d_in[2];
    const float*  lin_w = (const float*)d_in[3];
    float2* out = (float2*)d_out;

    int n = in_sizes[0] / 2;   // number of (q,p) pairs

    int per_block = TPB * EPT;
    int blocks = (n + per_block - 1) / per_block;
    sympnet_kernel<<<blocks, TPB>>>(x, act_w, bias_b, lin_w, out, n);
}